// round 2
// baseline (speedup 1.0000x reference)
#include <cuda_runtime.h>
#include <cuda_fp16.h>
#include <math.h>

#define L_   2048
#define E_   1024
#define H_   16
#define D_   64
#define MBL_ 2048

// ---------------- device scratch (static; allocation-free) -----------------
__device__ float  g_q[H_ * L_ * D_];            // [H][L][D]
__device__ float  g_k[H_ * L_ * D_];
__device__ float  g_v[H_ * L_ * D_];
__device__ float  g_ao[L_ * E_];                // attention out [L][H*D]
__device__ __half g_e[(size_t)H_ * L_ * L_];    // unnormalized exp(s - m_tile), fp16

// ============================================================================
// SGEMM core: C[128,64] tile of A[M,K] * B[N,K]^T. 256 threads, 8x4 micro.
// kTile=16, double-buffered smem, register-prefetched global loads.
// ============================================================================
#define SA_STR 132
#define SB_STR 68

__device__ __forceinline__ void gemm_core_128x64(
    const float* __restrict__ A, const float* __restrict__ B,
    int m0, int n0, int K, float acc[8][4], float* sA, float* sB)
{
    int tid = threadIdx.x;
    int ty = tid >> 4, tx = tid & 15;

    // A loader: 2 float4/thread (rows 0..63 then 64..127), cols (tid&3)*4
    int ar0 = tid >> 2;
    int ac  = (tid & 3) * 4;
    int ar1 = ar0 + 64;
    // B loader: 1 float4/thread (rows 0..63)
    int br = tid >> 2;
    int bc = ac;

    const float* Ar0 = A + (size_t)(m0 + ar0) * K + ac;
    const float* Ar1 = A + (size_t)(m0 + ar1) * K + ac;
    const float* Br  = B + (size_t)(n0 + br)  * K + bc;

    float4 pa0 = *(const float4*)(Ar0);
    float4 pa1 = *(const float4*)(Ar1);
    float4 pb  = *(const float4*)(Br);

#pragma unroll
    for (int i = 0; i < 8; i++)
#pragma unroll
        for (int j = 0; j < 4; j++) acc[i][j] = 0.f;

    // stage 0 store
    {
        float* s = sA;
        s[(ac+0)*SA_STR + ar0] = pa0.x; s[(ac+1)*SA_STR + ar0] = pa0.y;
        s[(ac+2)*SA_STR + ar0] = pa0.z; s[(ac+3)*SA_STR + ar0] = pa0.w;
        s[(ac+0)*SA_STR + ar1] = pa1.x; s[(ac+1)*SA_STR + ar1] = pa1.y;
        s[(ac+2)*SA_STR + ar1] = pa1.z; s[(ac+3)*SA_STR + ar1] = pa1.w;
        float* t = sB;
        t[(bc+0)*SB_STR + br] = pb.x; t[(bc+1)*SB_STR + br] = pb.y;
        t[(bc+2)*SB_STR + br] = pb.z; t[(bc+3)*SB_STR + br] = pb.w;
    }
    __syncthreads();

    int buf = 0;
    for (int kt = 0; kt < K; kt += 16) {
        bool more = (kt + 16) < K;
        if (more) {
            pa0 = *(const float4*)(Ar0 + kt + 16);
            pa1 = *(const float4*)(Ar1 + kt + 16);
            pb  = *(const float4*)(Br  + kt + 16);
        }
        const float* cA = sA + buf * (16 * SA_STR);
        const float* cB = sB + buf * (16 * SB_STR);
#pragma unroll 4
        for (int k = 0; k < 16; k++) {
            float a[8], b[4];
            *(float4*)&a[0] = *(const float4*)&cA[k * SA_STR + ty * 8];
            *(float4*)&a[4] = *(const float4*)&cA[k * SA_STR + ty * 8 + 4];
            *(float4*)&b[0] = *(const float4*)&cB[k * SB_STR + tx * 4];
#pragma unroll
            for (int i = 0; i < 8; i++)
#pragma unroll
                for (int j = 0; j < 4; j++)
                    acc[i][j] += a[i] * b[j];
        }
        if (more) {
            float* s = sA + (buf ^ 1) * (16 * SA_STR);
            s[(ac+0)*SA_STR + ar0] = pa0.x; s[(ac+1)*SA_STR + ar0] = pa0.y;
            s[(ac+2)*SA_STR + ar0] = pa0.z; s[(ac+3)*SA_STR + ar0] = pa0.w;
            s[(ac+0)*SA_STR + ar1] = pa1.x; s[(ac+1)*SA_STR + ar1] = pa1.y;
            s[(ac+2)*SA_STR + ar1] = pa1.z; s[(ac+3)*SA_STR + ar1] = pa1.w;
            float* t = sB + (buf ^ 1) * (16 * SB_STR);
            t[(bc+0)*SB_STR + br] = pb.x; t[(bc+1)*SB_STR + br] = pb.y;
            t[(bc+2)*SB_STR + br] = pb.z; t[(bc+3)*SB_STR + br] = pb.w;
        }
        __syncthreads();
        buf ^= 1;
    }
}

// QKV projections, output scattered to [H][L][D]
__global__ __launch_bounds__(256) void qkv_gemm(
    const float* __restrict__ x,
    const float* __restrict__ Wq,
    const float* __restrict__ Wk,
    const float* __restrict__ Wv)
{
    __shared__ float sA[2 * 16 * SA_STR];
    __shared__ float sB[2 * 16 * SB_STR];
    const float* B = (blockIdx.z == 0) ? Wq : (blockIdx.z == 1) ? Wk : Wv;
    float* C = (blockIdx.z == 0) ? g_q : (blockIdx.z == 1) ? g_k : g_v;

    int m0 = blockIdx.y * 128;
    int n0 = blockIdx.x * 64;
    float acc[8][4];
    gemm_core_128x64(x, B, m0, n0, E_, acc, sA, sB);

    int ty = threadIdx.x >> 4, tx = threadIdx.x & 15;
    float* Ch = C + (size_t)blockIdx.x * (L_ * 64);   // head = n0/64
#pragma unroll
    for (int i = 0; i < 8; i++) {
        int m = m0 + ty * 8 + i;
        *(float4*)(Ch + (size_t)m * 64 + tx * 4) =
            make_float4(acc[i][0], acc[i][1], acc[i][2], acc[i][3]);
    }
}

// Output projection: d_out[L,E] = g_ao @ Wo^T
__global__ __launch_bounds__(256) void out_gemm(
    const float* __restrict__ Wo, float* __restrict__ out)
{
    __shared__ float sA[2 * 16 * SA_STR];
    __shared__ float sB[2 * 16 * SB_STR];
    int m0 = blockIdx.y * 128;
    int n0 = blockIdx.x * 64;
    float acc[8][4];
    gemm_core_128x64(g_ao, Wo, m0, n0, E_, acc, sA, sB);

    int ty = threadIdx.x >> 4, tx = threadIdx.x & 15;
#pragma unroll
    for (int i = 0; i < 8; i++) {
        int m = m0 + ty * 8 + i;
        *(float4*)(out + (size_t)m * E_ + n0 + tx * 4) =
            make_float4(acc[i][0], acc[i][1], acc[i][2], acc[i][3]);
    }
}

// ============================================================================
// Attention. CTA (p, h) processes q-tiles {31-p, p} -> exactly 33 tile-units.
// Per q-tile: pass1 (online stats, e->fp16 gmem), pass2 (rescale+relu, PV).
// Row-major smem, float4 d/c-unrolled 4x4 microtiles.
// ============================================================================
__global__ __launch_bounds__(256) void attn_kernel(
    const float* __restrict__ bias, const float* __restrict__ tau)
{
    __shared__ float sQT[64 * 68];   // Q (pass1) / T (pass2), [row][col]
    __shared__ float sKV[64 * 68];   // K (pass1) / V (pass2), [kv-row][d]
    __shared__ float sbias[MBL_];
    __shared__ float mrow[64], zrow[64];
    __shared__ float mhist[64 * 33];

    int h   = blockIdx.y;
    int pr  = blockIdx.x;            // 0..15
    int tid = threadIdx.x;
    int ty  = tid >> 4, tx = tid & 15;
    float tauh = tau[h];
    const float scale = 0.125f;      // D^-0.5

    // stage bias row for this head
    for (int i = tid; i < MBL_ / 4; i += 256)
        *(float4*)&sbias[i * 4] = *(const float4*)&bias[h * MBL_ + i * 4];

    const float* qh = g_q + (size_t)h * L_ * D_;
    const float* kh = g_k + (size_t)h * L_ * D_;
    const float* vh = g_v + (size_t)h * L_ * D_;

    for (int which = 0; which < 2; which++) {
        int iq = which ? pr : (31 - pr);
        int q0 = iq * 64;
        int ntiles = iq + 1;

        // ---- load Q tile + init stats ----
        __syncthreads();             // prior tile's smem reads done
        {
#pragma unroll
            for (int pp = 0; pp < 4; pp++) {
                int f = tid + pp * 256;
                int r = f >> 4, c4 = (f & 15) * 4;
                *(float4*)&sQT[r * 68 + c4] =
                    *(const float4*)(qh + (size_t)(q0 + r) * 64 + c4);
            }
            if (tid < 64) { mrow[tid] = -INFINITY; zrow[tid] = 0.f; }
        }

        // ==================== PASS 1 ====================
        float4 kreg[4];
#pragma unroll
        for (int pp = 0; pp < 4; pp++) {
            int f = tid + pp * 256;
            kreg[pp] = *(const float4*)(kh + (size_t)((f >> 4)) * 64 + ((f & 15) * 4));
        }
        for (int jt = 0; jt < ntiles; jt++) {
            int k0 = jt * 64;
            __syncthreads();         // prev compute done reading sKV; Q/stats visible
#pragma unroll
            for (int pp = 0; pp < 4; pp++) {
                int f = tid + pp * 256;
                *(float4*)&sKV[(f >> 4) * 68 + (f & 15) * 4] = kreg[pp];
            }
            if (jt + 1 < ntiles) {
                int k0n = (jt + 1) * 64;
#pragma unroll
                for (int pp = 0; pp < 4; pp++) {
                    int f = tid + pp * 256;
                    kreg[pp] = *(const float4*)(kh + (size_t)(k0n + (f >> 4)) * 64 + ((f & 15) * 4));
                }
            }
            __syncthreads();         // sKV ready

            // S = Q K^T, 4x4 per thread, d unrolled by 4 (float4)
            float s[4][4];
#pragma unroll
            for (int i = 0; i < 4; i++)
#pragma unroll
                for (int j = 0; j < 4; j++) s[i][j] = 0.f;
#pragma unroll 4
            for (int d4 = 0; d4 < 64; d4 += 4) {
                float a[4][4], b[4][4];
#pragma unroll
                for (int i = 0; i < 4; i++)
                    *(float4*)&a[i][0] = *(const float4*)&sQT[(ty * 4 + i) * 68 + d4];
#pragma unroll
                for (int j = 0; j < 4; j++)
                    *(float4*)&b[j][0] = *(const float4*)&sKV[(tx * 4 + j) * 68 + d4];
#pragma unroll
                for (int u = 0; u < 4; u++)
#pragma unroll
                    for (int i = 0; i < 4; i++)
#pragma unroll
                        for (int j = 0; j < 4; j++)
                            s[i][j] += a[i][u] * b[j][u];
            }

            // scale + bias + causal mask
#pragma unroll
            for (int i = 0; i < 4; i++) {
                int q = q0 + ty * 4 + i;
#pragma unroll
                for (int j = 0; j < 4; j++) {
                    int dist = q - (k0 + tx * 4 + j);
                    s[i][j] = (dist >= 0) ? (s[i][j] * scale + sbias[dist]) : -INFINITY;
                }
            }

            // per-row online stats (16-lane half-warp owns a row), store e fp16
#pragma unroll
            for (int i = 0; i < 4; i++) {
                int r = ty * 4 + i;
                float mold = mrow[r];
                float rmax = fmaxf(fmaxf(s[i][0], s[i][1]), fmaxf(s[i][2], s[i][3]));
#pragma unroll
                for (int o = 8; o >= 1; o >>= 1)
                    rmax = fmaxf(rmax, __shfl_xor_sync(0xffffffffu, rmax, o));
                float mnew = fmaxf(mold, rmax);
                float e0 = __expf(s[i][0] - mnew);
                float e1 = __expf(s[i][1] - mnew);
                float e2 = __expf(s[i][2] - mnew);
                float e3 = __expf(s[i][3] - mnew);
                __half2 p0 = __floats2half2_rn(e0, e1);
                __half2 p1 = __floats2half2_rn(e2, e3);
                uint2 w;
                w.x = *(unsigned*)&p0;
                w.y = *(unsigned*)&p1;
                *(uint2*)&g_e[((size_t)(h * L_ + q0 + r)) * L_ + k0 + tx * 4] = w;
                float rs = e0 + e1 + e2 + e3;
#pragma unroll
                for (int o = 8; o >= 1; o >>= 1)
                    rs += __shfl_xor_sync(0xffffffffu, rs, o);
                if (tx == 0) {
                    zrow[r] = zrow[r] * __expf(mold - mnew) + rs;
                    mrow[r] = mnew;
                    mhist[r * 33 + jt] = mnew;
                }
            }
        }
        __syncthreads();             // stats final

        // ==================== PASS 2 ====================
        float mf[4], iz[4], tt[4];
#pragma unroll
        for (int i = 0; i < 4; i++) {
            int r = ty * 4 + i;
            mf[i] = mrow[r];
            iz[i] = 1.f / zrow[r];
            tt[i] = tauh / (float)(q0 + r + 1);
        }
        float o[4][4];
#pragma unroll
        for (int i = 0; i < 4; i++)
#pragma unroll
            for (int j = 0; j < 4; j++) o[i][j] = 0.f;

        float4 vreg[4];
#pragma unroll
        for (int pp = 0; pp < 4; pp++) {
            int f = tid + pp * 256;
            vreg[pp] = *(const float4*)(vh + (size_t)((f >> 4)) * 64 + ((f & 15) * 4));
        }
        for (int jt = 0; jt < ntiles; jt++) {
            int k0 = jt * 64;
            // rescale stored exponentials, apply elastic-softmax relu
            float t[4][4];
#pragma unroll
            for (int i = 0; i < 4; i++) {
                int r = ty * 4 + i;
                uint2 w = *(const uint2*)&g_e[((size_t)(h * L_ + q0 + r)) * L_ + k0 + tx * 4];
                __half2 p0 = *(__half2*)&w.x;
                __half2 p1 = *(__half2*)&w.y;
                float2 e01 = __half22float2(p0);
                float2 e23 = __half22float2(p1);
                float f = __expf(mhist[r * 33 + jt] - mf[i]) * iz[i];
                t[i][0] = fmaxf(e01.x * f + tt[i], 0.f);
                t[i][1] = fmaxf(e01.y * f + tt[i], 0.f);
                t[i][2] = fmaxf(e23.x * f + tt[i], 0.f);
                t[i][3] = fmaxf(e23.y * f + tt[i], 0.f);
            }
            __syncthreads();         // prev PV done reading sQT/sKV
#pragma unroll
            for (int i = 0; i < 4; i++)
                *(float4*)&sQT[(ty * 4 + i) * 68 + tx * 4] =
                    make_float4(t[i][0], t[i][1], t[i][2], t[i][3]);
#pragma unroll
            for (int pp = 0; pp < 4; pp++) {
                int f = tid + pp * 256;
                *(float4*)&sKV[(f >> 4) * 68 + (f & 15) * 4] = vreg[pp];
            }
            if (jt + 1 < ntiles) {
                int k0n = (jt + 1) * 64;
#pragma unroll
                for (int pp = 0; pp < 4; pp++) {
                    int f = tid + pp * 256;
                    vreg[pp] = *(const float4*)(vh + (size_t)(k0n + (f >> 4)) * 64 + ((f & 15) * 4));
                }
            }
            __syncthreads();         // sQT(T), sKV(V) ready

            // O += T @ V, c unrolled by 4
#pragma unroll 4
            for (int c4 = 0; c4 < 64; c4 += 4) {
                float tv[4][4], vv[4][4];
#pragma unroll
                for (int i = 0; i < 4; i++)
                    *(float4*)&tv[i][0] = *(const float4*)&sQT[(ty * 4 + i) * 68 + c4];
#pragma unroll
                for (int u = 0; u < 4; u++)
                    *(float4*)&vv[u][0] = *(const float4*)&sKV[(c4 + u) * 68 + tx * 4];
#pragma unroll
                for (int u = 0; u < 4; u++)
#pragma unroll
                    for (int i = 0; i < 4; i++)
#pragma unroll
                        for (int j = 0; j < 4; j++)
                            o[i][j] += tv[i][u] * vv[u][j];
            }
        }

        // write O to g_ao[l][h*64+d]
#pragma unroll
        for (int i = 0; i < 4; i++) {
            int q = q0 + ty * 4 + i;
            *(float4*)&g_ao[(size_t)q * E_ + h * 64 + tx * 4] =
                make_float4(o[i][0], o[i][1], o[i][2], o[i][3]);
        }
    }
}

// ============================================================================
extern "C" void kernel_launch(void* const* d_in, const int* in_sizes, int n_in,
                              void* d_out, int out_size)
{
    (void)in_sizes; (void)n_in; (void)out_size;
    const float* x    = (const float*)d_in[0];
    const float* Wq   = (const float*)d_in[1];
    const float* Wk   = (const float*)d_in[2];
    const float* Wv   = (const float*)d_in[3];
    const float* Wo   = (const float*)d_in[4];
    const float* bias = (const float*)d_in[5];
    const float* tau  = (const float*)d_in[6];
    float* out = (float*)d_out;

    qkv_gemm<<<dim3(E_ / 64, L_ / 128, 3), 256>>>(x, Wq, Wk, Wv);
    attn_kernel<<<dim3(16, H_), 256>>>(bias, tau);
    out_gemm<<<dim3(E_ / 64, L_ / 128), 256>>>(Wo, out);
}

// round 5
// speedup vs baseline: 1.7482x; 1.7482x over previous
#include <cuda_runtime.h>
#include <cuda_bf16.h>
#include <cstdint>
#include <math.h>

#define L_   2048
#define E_   1024
#define H_   16
#define D_   64
#define MBL_ 2048

// ---------------- device scratch (static; allocation-free) -----------------
__device__ float g_q[H_ * L_ * D_];             // [H][L][D]
__device__ float g_k[H_ * L_ * D_];
__device__ float g_v[H_ * L_ * D_];
__device__ float g_ao[L_ * E_];                 // attention out [L][H*D]
__device__ float g_e[(size_t)H_ * L_ * L_];     // unnormalized exp(s - m_tile)

// bf16 hi/lo splits for tensor-core GEMMs
__device__ __nv_bfloat16 g_xhi[L_ * E_],  g_xlo[L_ * E_];
__device__ __nv_bfloat16 g_whi[4 * E_ * E_], g_wlo[4 * E_ * E_];   // q,k,v,o
__device__ __nv_bfloat16 g_aohi[L_ * E_], g_aolo[L_ * E_];

// ============================ PTX helpers (sm_80+ only) =====================
__device__ __forceinline__ uint32_t smem_u32(const void* p) {
    uint32_t a;
    asm("{ .reg .u64 t; cvta.to.shared.u64 t, %1; cvt.u32.u64 %0, t; }"
        : "=r"(a) : "l"(p));
    return a;
}
__device__ __forceinline__ void cp16(uint32_t dst, const void* src) {
    asm volatile("cp.async.cg.shared.global [%0], [%1], 16;" :: "r"(dst), "l"(src));
}
#define CP_COMMIT()  asm volatile("cp.async.commit_group;" ::: "memory")
#define CP_WAIT(n)   asm volatile("cp.async.wait_group %0;" :: "n"(n) : "memory")

__device__ __forceinline__ void ldsm4(uint32_t a[4], uint32_t addr) {
    asm volatile("ldmatrix.sync.aligned.m8n8.x4.shared.b16 {%0,%1,%2,%3}, [%4];"
        : "=r"(a[0]), "=r"(a[1]), "=r"(a[2]), "=r"(a[3]) : "r"(addr));
}
__device__ __forceinline__ void ldsm2(uint32_t a[2], uint32_t addr) {
    asm volatile("ldmatrix.sync.aligned.m8n8.x2.shared.b16 {%0,%1}, [%2];"
        : "=r"(a[0]), "=r"(a[1]) : "r"(addr));
}
__device__ __forceinline__ void mma16816(float d[4], const uint32_t a[4], const uint32_t b[2]) {
    asm volatile("mma.sync.aligned.m16n8k16.row.col.f32.bf16.bf16.f32 "
        "{%0,%1,%2,%3}, {%4,%5,%6,%7}, {%8,%9}, {%0,%1,%2,%3};"
        : "+f"(d[0]), "+f"(d[1]), "+f"(d[2]), "+f"(d[3])
        : "r"(a[0]), "r"(a[1]), "r"(a[2]), "r"(a[3]), "r"(b[0]), "r"(b[1]));
}

// ============================================================================
// fp32 -> bf16 hi/lo split.  which: 0 x, 1..4 W(q,k,v,o), 5 g_ao
// ============================================================================
__global__ __launch_bounds__(256) void conv_pair(const float* __restrict__ src, int which)
{
    const float* s;
    __nv_bfloat16 *hi, *lo;
    if (which == 0)      { s = src;  hi = g_xhi;  lo = g_xlo;  }
    else if (which <= 4) { s = src;  hi = g_whi + (size_t)(which - 1) * (E_ * E_);
                                     lo = g_wlo + (size_t)(which - 1) * (E_ * E_); }
    else                 { s = g_ao; hi = g_aohi; lo = g_aolo; }

    int i = blockIdx.x * 256 + threadIdx.x;
    float4 v = ((const float4*)s)[i];
    __nv_bfloat16 h0 = __float2bfloat16(v.x);
    __nv_bfloat16 h1 = __float2bfloat16(v.y);
    __nv_bfloat16 h2 = __float2bfloat16(v.z);
    __nv_bfloat16 h3 = __float2bfloat16(v.w);
    __nv_bfloat16 l0 = __float2bfloat16(v.x - __bfloat162float(h0));
    __nv_bfloat16 l1 = __float2bfloat16(v.y - __bfloat162float(h1));
    __nv_bfloat16 l2 = __float2bfloat16(v.z - __bfloat162float(h2));
    __nv_bfloat16 l3 = __float2bfloat16(v.w - __bfloat162float(h3));
    __nv_bfloat162* h2p = (__nv_bfloat162*)(hi + i * 4);
    __nv_bfloat162* l2p = (__nv_bfloat162*)(lo + i * 4);
    h2p[0] = __nv_bfloat162(h0, h1); h2p[1] = __nv_bfloat162(h2, h3);
    l2p[0] = __nv_bfloat162(l0, l1); l2p[1] = __nv_bfloat162(l2, l3);
}

// ============================================================================
// bf16x3 GEMM on mma.sync: C[128,128] = A[M,K] * B[N,K]^T
// 256 thr = 8 warps (2x4), warp tile 64x32, BK=64 (128B rows, xor-swizzled),
// cp.async double-buffered.  mode 0: x*W[z] -> g_q/g_k/g_v; mode 1: ao*Wo->out
// ============================================================================
#define BK    64
#define NCHK  (E_ / BK)             // 16
#define TILEB (128 * BK * 2)        // 16 KB per 128xBK bf16 tile
#define STAGEB (4 * TILEB)          // Ahi,Alo,Bhi,Blo = 64 KB
#define SMEM_MMA (2 * STAGEB)       // 128 KB

__device__ __forceinline__ void load_tile_async(
    uint32_t dst, const __nv_bfloat16* src, int row0, int kt, int tid)
{
#pragma unroll
    for (int it = 0; it < 4; it++) {
        int c = tid + it * 256;                 // 0..1023: 128 rows x 8 chunks
        int row = c >> 3;
        int ch  = c & 7;
        const __nv_bfloat16* sp = src + (size_t)(row0 + row) * E_ + kt + ch * 8;
        uint32_t sw = row * 128 + ((ch ^ (row & 7)) << 4);
        cp16(dst + sw, sp);
    }
}

__global__ __launch_bounds__(256) void mma_gemm(int mode, float* __restrict__ out)
{
    extern __shared__ char smem[];
    uint32_t sbase = smem_u32(smem);
    int tid  = threadIdx.x;
    int lane = tid & 31;
    int w    = tid >> 5;
    int wm   = w >> 2;               // 0..1
    int wn   = w & 3;                // 0..3
    int z    = blockIdx.z;
    int m0   = blockIdx.y * 128;
    int n0   = blockIdx.x * 128;

    const __nv_bfloat16* Ahi = (mode == 0) ? g_xhi : g_aohi;
    const __nv_bfloat16* Alo = (mode == 0) ? g_xlo : g_aolo;
    int wsel = (mode == 0) ? z : 3;
    const __nv_bfloat16* Bhi = g_whi + (size_t)wsel * (E_ * E_);
    const __nv_bfloat16* Blo = g_wlo + (size_t)wsel * (E_ * E_);

    float acc[4][4][4];
#pragma unroll
    for (int mi = 0; mi < 4; mi++)
#pragma unroll
        for (int ni = 0; ni < 4; ni++)
#pragma unroll
            for (int r = 0; r < 4; r++) acc[mi][ni][r] = 0.f;

    // per-lane ldmatrix row bases (row&7 == lane&7 for all frags)
    int rl = lane & 7;
    int ai = lane >> 3;              // 0..3: A matrix select
    int aci = ai >> 1;               // chunk half (k+8)
    int arow[4];
#pragma unroll
    for (int mi = 0; mi < 4; mi++)
        arow[mi] = (wm * 64 + mi * 16 + (ai & 1) * 8 + rl) * 128;
    int bi = (lane >> 3) & 1;        // B matrix select (lanes 16+ mirror 0-15)
    int brow[4];
#pragma unroll
    for (int ni = 0; ni < 4; ni++)
        brow[ni] = (wn * 32 + ni * 8 + rl) * 128;

    // prologue: stage 0
    load_tile_async(sbase + 0 * TILEB, Ahi, m0, 0, tid);
    load_tile_async(sbase + 1 * TILEB, Alo, m0, 0, tid);
    load_tile_async(sbase + 2 * TILEB, Bhi, n0, 0, tid);
    load_tile_async(sbase + 3 * TILEB, Blo, n0, 0, tid);
    CP_COMMIT();

    for (int kt = 0; kt < NCHK; kt++) {
        bool more = (kt + 1) < NCHK;
        if (more) {
            uint32_t nb = sbase + ((kt + 1) & 1) * STAGEB;
            int kk = (kt + 1) * BK;
            load_tile_async(nb + 0 * TILEB, Ahi, m0, kk, tid);
            load_tile_async(nb + 1 * TILEB, Alo, m0, kk, tid);
            load_tile_async(nb + 2 * TILEB, Bhi, n0, kk, tid);
            load_tile_async(nb + 3 * TILEB, Blo, n0, kk, tid);
            CP_COMMIT();
            CP_WAIT(1);
        } else {
            CP_WAIT(0);
        }
        __syncthreads();

        uint32_t st = sbase + (kt & 1) * STAGEB;
        // 3 terms: (hi,hi), (hi,lo), (lo,hi)
#pragma unroll
        for (int t = 0; t < 3; t++) {
            uint32_t uA = st + ((t == 2) ? TILEB : 0);
            uint32_t uB = st + 2 * TILEB + ((t == 1) ? TILEB : 0);
#pragma unroll
            for (int ks = 0; ks < 4; ks++) {
                uint32_t af[4][4], bf[4][2];
#pragma unroll
                for (int mi = 0; mi < 4; mi++)
                    ldsm4(af[mi], uA + arow[mi] + (((ks * 2 + aci) ^ rl) << 4));
#pragma unroll
                for (int ni = 0; ni < 4; ni++)
                    ldsm2(bf[ni], uB + brow[ni] + (((ks * 2 + bi) ^ rl) << 4));
#pragma unroll
                for (int mi = 0; mi < 4; mi++)
#pragma unroll
                    for (int ni = 0; ni < 4; ni++)
                        mma16816(acc[mi][ni], af[mi], bf[ni]);
            }
        }
        __syncthreads();
    }

    // epilogue: thread owns (m = mi*16 + lane/4 [+8], n = ni*8 + (lane%4)*2)
    int mrow = m0 + wm * 64 + (lane >> 2);
    int ncol = n0 + wn * 32 + (lane & 3) * 2;
#pragma unroll
    for (int mi = 0; mi < 4; mi++) {
#pragma unroll
        for (int ni = 0; ni < 4; ni++) {
            int n = ncol + ni * 8;
#pragma unroll
            for (int half = 0; half < 2; half++) {
                int m = mrow + mi * 16 + half * 8;
                float2 v = make_float2(acc[mi][ni][half * 2], acc[mi][ni][half * 2 + 1]);
                if (mode == 0) {
                    float* C = (z == 0) ? g_q : (z == 1) ? g_k : g_v;
                    *(float2*)(C + (size_t)(n >> 6) * (L_ * 64) + (size_t)m * 64 + (n & 63)) = v;
                } else {
                    *(float2*)(out + (size_t)m * E_ + n) = v;
                }
            }
        }
    }
}

// ============================================================================
// Attention (round-1 version, verbatim). One CTA = (head h, 64-query tile iq).
// ============================================================================
__global__ __launch_bounds__(256) void attn_kernel(
    const float* __restrict__ bias, const float* __restrict__ tau)
{
    __shared__ float QTs[64 * 68];   // pass1: Q^T [d][r]; pass2 reused: T^T [c][r]
    __shared__ float KVs[64 * 68];   // pass1: K^T [d][c]; pass2: V [c][d]
    __shared__ float mrow[64], zrow[64];
    __shared__ float mhist[64 * 32];

    int h  = blockIdx.y;
    int iq = gridDim.x - 1 - blockIdx.x;   // heavy (late) q-tiles launch first
    int q0 = iq * 64;
    int tid = threadIdx.x;
    int ty = tid >> 4, tx = tid & 15;
    float tauh = tau[h];
    const float scale = 0.125f;
    int ntiles = iq + 1;

    const float* qbase = g_q + (size_t)h * L_ * D_ + (size_t)q0 * D_;
#pragma unroll
    for (int p = 0; p < 4; p++) {
        int idx = tid + p * 256;
        int r = idx >> 4;
        int d4 = (idx & 15) * 4;
        float4 v = *(const float4*)(qbase + r * D_ + d4);
        QTs[(d4 + 0) * 68 + r] = v.x;
        QTs[(d4 + 1) * 68 + r] = v.y;
        QTs[(d4 + 2) * 68 + r] = v.z;
        QTs[(d4 + 3) * 68 + r] = v.w;
    }
    if (tid < 64) { mrow[tid] = -INFINITY; zrow[tid] = 0.f; }

    // ==================== PASS 1 ====================
    for (int jt = 0; jt < ntiles; jt++) {
        int k0 = jt * 64;
        const float* kbase = g_k + (size_t)h * L_ * D_ + (size_t)k0 * D_;
        __syncthreads();
#pragma unroll
        for (int p = 0; p < 4; p++) {
            int idx = tid + p * 256;
            int r = idx >> 4;
            int d4 = (idx & 15) * 4;
            float4 v = *(const float4*)(kbase + r * D_ + d4);
            KVs[(d4 + 0) * 68 + r] = v.x;
            KVs[(d4 + 1) * 68 + r] = v.y;
            KVs[(d4 + 2) * 68 + r] = v.z;
            KVs[(d4 + 3) * 68 + r] = v.w;
        }
        __syncthreads();

        float s[4][4];
#pragma unroll
        for (int i = 0; i < 4; i++)
#pragma unroll
            for (int j = 0; j < 4; j++) s[i][j] = 0.f;
#pragma unroll 16
        for (int d = 0; d < 64; d++) {
            float4 a = *(const float4*)&QTs[d * 68 + ty * 4];
            float4 b = *(const float4*)&KVs[d * 68 + tx * 4];
            float av[4] = {a.x, a.y, a.z, a.w};
            float bv[4] = {b.x, b.y, b.z, b.w};
#pragma unroll
            for (int i = 0; i < 4; i++)
#pragma unroll
                for (int j = 0; j < 4; j++)
                    s[i][j] += av[i] * bv[j];
        }

#pragma unroll
        for (int i = 0; i < 4; i++) {
            int q = q0 + ty * 4 + i;
#pragma unroll
            for (int j = 0; j < 4; j++) {
                int k = k0 + tx * 4 + j;
                int dist = q - k;
                s[i][j] = (dist >= 0) ? (s[i][j] * scale + bias[h * MBL_ + dist])
                                      : -INFINITY;
            }
        }

#pragma unroll
        for (int i = 0; i < 4; i++) {
            int r = ty * 4 + i;
            float mold = mrow[r];
            float rmax = fmaxf(fmaxf(s[i][0], s[i][1]), fmaxf(s[i][2], s[i][3]));
#pragma unroll
            for (int o = 8; o >= 1; o >>= 1)
                rmax = fmaxf(rmax, __shfl_xor_sync(0xffffffffu, rmax, o));
            float mnew = fmaxf(mold, rmax);
            float e0 = __expf(s[i][0] - mnew);
            float e1 = __expf(s[i][1] - mnew);
            float e2 = __expf(s[i][2] - mnew);
            float e3 = __expf(s[i][3] - mnew);
            *(float4*)(g_e + ((size_t)h * L_ + q0 + r) * L_ + k0 + tx * 4) =
                make_float4(e0, e1, e2, e3);
            float rs = e0 + e1 + e2 + e3;
#pragma unroll
            for (int o = 8; o >= 1; o >>= 1)
                rs += __shfl_xor_sync(0xffffffffu, rs, o);
            if (tx == 0) {
                zrow[r] = zrow[r] * __expf(mold - mnew) + rs;
                mrow[r] = mnew;
                mhist[r * 32 + jt] = mnew;
            }
        }
    }
    __syncthreads();

    // ==================== PASS 2 ====================
    float mfin[4], invz[4], taut[4];
#pragma unroll
    for (int i = 0; i < 4; i++) {
        int r = ty * 4 + i;
        mfin[i] = mrow[r];
        invz[i] = 1.f / zrow[r];
        taut[i] = tauh / (float)(q0 + r + 1);
    }
    float o[4][4];
#pragma unroll
    for (int i = 0; i < 4; i++)
#pragma unroll
        for (int j = 0; j < 4; j++) o[i][j] = 0.f;

    for (int jt = 0; jt < ntiles; jt++) {
        int k0 = jt * 64;
        float t[4][4];
#pragma unroll
        for (int i = 0; i < 4; i++) {
            int r = ty * 4 + i;
            float4 ev = *(const float4*)(g_e + ((size_t)h * L_ + q0 + r) * L_ + k0 + tx * 4);
            float f = __expf(mhist[r * 32 + jt] - mfin[i]) * invz[i];
            t[i][0] = fmaxf(ev.x * f + taut[i], 0.f);
            t[i][1] = fmaxf(ev.y * f + taut[i], 0.f);
            t[i][2] = fmaxf(ev.z * f + taut[i], 0.f);
            t[i][3] = fmaxf(ev.w * f + taut[i], 0.f);
        }
        __syncthreads();
#pragma unroll
        for (int i = 0; i < 4; i++)
#pragma unroll
            for (int j = 0; j < 4; j++)
                QTs[(tx * 4 + j) * 68 + ty * 4 + i] = t[i][j];
        const float* vbase = g_v + (size_t)h * L_ * D_ + (size_t)k0 * D_;
#pragma unroll
        for (int p = 0; p < 4; p++) {
            int idx = tid + p * 256;
            int r = idx >> 4;
            int d4 = (idx & 15) * 4;
            *(float4*)&KVs[r * 68 + d4] = *(const float4*)(vbase + r * D_ + d4);
        }
        __syncthreads();
#pragma unroll 8
        for (int c = 0; c < 64; c++) {
            float4 tv = *(const float4*)&QTs[c * 68 + ty * 4];
            float4 vv = *(const float4*)&KVs[c * 68 + tx * 4];
            float ta[4] = {tv.x, tv.y, tv.z, tv.w};
            float va[4] = {vv.x, vv.y, vv.z, vv.w};
#pragma unroll
            for (int i = 0; i < 4; i++)
#pragma unroll
                for (int j = 0; j < 4; j++)
                    o[i][j] += ta[i] * va[j];
        }
    }

#pragma unroll
    for (int i = 0; i < 4; i++) {
        int q = q0 + ty * 4 + i;
        *(float4*)&g_ao[(size_t)q * E_ + h * 64 + tx * 4] =
            make_float4(o[i][0], o[i][1], o[i][2], o[i][3]);
    }
}

// ============================================================================
extern "C" void kernel_launch(void* const* d_in, const int* in_sizes, int n_in,
                              void* d_out, int out_size)
{
    (void)in_sizes; (void)n_in; (void)out_size;
    const float* x    = (const float*)d_in[0];
    const float* Wq   = (const float*)d_in[1];
    const float* Wk   = (const float*)d_in[2];
    const float* Wv   = (const float*)d_in[3];
    const float* Wo   = (const float*)d_in[4];
    const float* bias = (const float*)d_in[5];
    const float* tau  = (const float*)d_in[6];
    float* out = (float*)d_out;

    cudaFuncSetAttribute(mma_gemm, cudaFuncAttributeMaxDynamicSharedMemorySize, SMEM_MMA);

    // hi/lo bf16 splits
    conv_pair<<<(L_ * E_ / 4) / 256, 256>>>(x,  0);
    conv_pair<<<(E_ * E_ / 4) / 256, 256>>>(Wq, 1);
    conv_pair<<<(E_ * E_ / 4) / 256, 256>>>(Wk, 2);
    conv_pair<<<(E_ * E_ / 4) / 256, 256>>>(Wv, 3);
    conv_pair<<<(E_ * E_ / 4) / 256, 256>>>(Wo, 4);

    // QKV projections on tensor cores (mma.sync)
    mma_gemm<<<dim3(E_ / 128, L_ / 128, 3), 256, SMEM_MMA>>>(0, nullptr);

    // Attention
    attn_kernel<<<dim3(L_ / 64, H_), 256>>>(bias, tau);

    // Output projection
    conv_pair<<<(L_ * E_ / 4) / 256, 256>>>(nullptr, 5);
    mma_gemm<<<dim3(E_ / 128, L_ / 128, 1), 256, SMEM_MMA>>>(1, out);
}

// round 6
// speedup vs baseline: 2.8664x; 1.6396x over previous
#include <cuda_runtime.h>
#include <cuda_bf16.h>
#include <cuda_fp16.h>
#include <cstdint>
#include <math.h>

#define L_   2048
#define E_   1024
#define H_   16
#define D_   64
#define MBL_ 2048

// ---------------- device scratch (static; allocation-free) -----------------
__device__ __half g_e[(size_t)H_ * L_ * L_];    // exp(s), unnormalized, fp16

// bf16 hi/lo tensors
__device__ __nv_bfloat16 g_xhi[L_ * E_],  g_xlo[L_ * E_];
__device__ __nv_bfloat16 g_whi[4 * E_ * E_], g_wlo[4 * E_ * E_];   // q,k,v,o
__device__ __nv_bfloat16 g_aohi[L_ * E_], g_aolo[L_ * E_];
__device__ __nv_bfloat16 g_qhi[H_ * L_ * D_], g_qlo[H_ * L_ * D_]; // [H][L][64]
__device__ __nv_bfloat16 g_khi[H_ * L_ * D_], g_klo[H_ * L_ * D_];
__device__ __nv_bfloat16 g_vhi[H_ * L_ * D_], g_vlo[H_ * L_ * D_];

// ============================ PTX helpers (sm_80+) ==========================
__device__ __forceinline__ uint32_t smem_u32(const void* p) {
    uint32_t a;
    asm("{ .reg .u64 t; cvta.to.shared.u64 t, %1; cvt.u32.u64 %0, t; }"
        : "=r"(a) : "l"(p));
    return a;
}
__device__ __forceinline__ void cp16(uint32_t dst, const void* src) {
    asm volatile("cp.async.cg.shared.global [%0], [%1], 16;" :: "r"(dst), "l"(src));
}
#define CP_COMMIT()  asm volatile("cp.async.commit_group;" ::: "memory")
#define CP_WAIT(n)   asm volatile("cp.async.wait_group %0;" :: "n"(n) : "memory")

__device__ __forceinline__ void ldsm4(uint32_t a[4], uint32_t addr) {
    asm volatile("ldmatrix.sync.aligned.m8n8.x4.shared.b16 {%0,%1,%2,%3}, [%4];"
        : "=r"(a[0]), "=r"(a[1]), "=r"(a[2]), "=r"(a[3]) : "r"(addr));
}
__device__ __forceinline__ void ldsm2(uint32_t a[2], uint32_t addr) {
    asm volatile("ldmatrix.sync.aligned.m8n8.x2.shared.b16 {%0,%1}, [%2];"
        : "=r"(a[0]), "=r"(a[1]) : "r"(addr));
}
__device__ __forceinline__ void ldsm2t(uint32_t a[2], uint32_t addr) {
    asm volatile("ldmatrix.sync.aligned.m8n8.x2.trans.shared.b16 {%0,%1}, [%2];"
        : "=r"(a[0]), "=r"(a[1]) : "r"(addr));
}
__device__ __forceinline__ void mma16816(float d[4], const uint32_t a[4], const uint32_t b[2]) {
    asm volatile("mma.sync.aligned.m16n8k16.row.col.f32.bf16.bf16.f32 "
        "{%0,%1,%2,%3}, {%4,%5,%6,%7}, {%8,%9}, {%0,%1,%2,%3};"
        : "+f"(d[0]), "+f"(d[1]), "+f"(d[2]), "+f"(d[3])
        : "r"(a[0]), "r"(a[1]), "r"(a[2]), "r"(a[3]), "r"(b[0]), "r"(b[1]));
}

// fast exp on FMA pipe (no MUFU): magic rounding + deg-5 poly + exponent splice
__device__ __forceinline__ float fexp(float x) {
    float z  = fmaxf(x, -80.f) * 1.4426950408889634f;
    float fz = z + 12582912.f;                   // 1.5*2^23: round-to-nearest
    int   n  = __float_as_int(fz) - 0x4B400000;
    float f  = z - (float)n;                     // exact, f in [-0.5, 0.5]
    float p  = 1.3333558146428443e-3f;
    p = fmaf(p, f, 9.6181291076284772e-3f);
    p = fmaf(p, f, 5.5504108664821580e-2f);
    p = fmaf(p, f, 2.4022650695910071e-1f);
    p = fmaf(p, f, 6.9314718055994531e-1f);
    p = fmaf(p, f, 1.0f);
    return p * __int_as_float((n + 127) << 23);
}

// ============================================================================
// fp32 -> bf16 hi/lo split.  which: 0 x, 1..4 W(q,k,v,o)
// ============================================================================
__global__ __launch_bounds__(256) void conv_pair(const float* __restrict__ src, int which)
{
    __nv_bfloat16 *hi, *lo;
    if (which == 0) { hi = g_xhi; lo = g_xlo; }
    else            { hi = g_whi + (size_t)(which - 1) * (E_ * E_);
                      lo = g_wlo + (size_t)(which - 1) * (E_ * E_); }

    int i = blockIdx.x * 256 + threadIdx.x;
    float4 v = ((const float4*)src)[i];
    __nv_bfloat16 h0 = __float2bfloat16(v.x);
    __nv_bfloat16 h1 = __float2bfloat16(v.y);
    __nv_bfloat16 h2 = __float2bfloat16(v.z);
    __nv_bfloat16 h3 = __float2bfloat16(v.w);
    __nv_bfloat16 l0 = __float2bfloat16(v.x - __bfloat162float(h0));
    __nv_bfloat16 l1 = __float2bfloat16(v.y - __bfloat162float(h1));
    __nv_bfloat16 l2 = __float2bfloat16(v.z - __bfloat162float(h2));
    __nv_bfloat16 l3 = __float2bfloat16(v.w - __bfloat162float(h3));
    __nv_bfloat162* h2p = (__nv_bfloat162*)(hi + i * 4);
    __nv_bfloat162* l2p = (__nv_bfloat162*)(lo + i * 4);
    h2p[0] = __nv_bfloat162(h0, h1); h2p[1] = __nv_bfloat162(h2, h3);
    l2p[0] = __nv_bfloat162(l0, l1); l2p[1] = __nv_bfloat162(l2, l3);
}

// ============================================================================
// bf16x3 GEMM on mma.sync: C[128,128] = A[M,K] * B[N,K]^T
// mode 0: x*W[z] -> q/k/v bf16 hi/lo [H][L][64];  mode 1: ao*Wo -> out fp32
// ============================================================================
#define BK    64
#define NCHK  (E_ / BK)
#define TILEB (128 * BK * 2)
#define STAGEB (4 * TILEB)
#define SMEM_MMA (2 * STAGEB)

__device__ __forceinline__ void load_tile_async(
    uint32_t dst, const __nv_bfloat16* src, int row0, int kt, int tid)
{
#pragma unroll
    for (int it = 0; it < 4; it++) {
        int c = tid + it * 256;
        int row = c >> 3;
        int ch  = c & 7;
        const __nv_bfloat16* sp = src + (size_t)(row0 + row) * E_ + kt + ch * 8;
        uint32_t sw = row * 128 + ((ch ^ (row & 7)) << 4);
        cp16(dst + sw, sp);
    }
}

__global__ __launch_bounds__(256) void mma_gemm(int mode, float* __restrict__ out)
{
    extern __shared__ char smem[];
    uint32_t sbase = smem_u32(smem);
    int tid  = threadIdx.x;
    int lane = tid & 31;
    int w    = tid >> 5;
    int wm   = w >> 2;
    int wn   = w & 3;
    int z    = blockIdx.z;
    int m0   = blockIdx.y * 128;
    int n0   = blockIdx.x * 128;

    const __nv_bfloat16* Ahi = (mode == 0) ? g_xhi : g_aohi;
    const __nv_bfloat16* Alo = (mode == 0) ? g_xlo : g_aolo;
    int wsel = (mode == 0) ? z : 3;
    const __nv_bfloat16* Bhi = g_whi + (size_t)wsel * (E_ * E_);
    const __nv_bfloat16* Blo = g_wlo + (size_t)wsel * (E_ * E_);

    float acc[4][4][4];
#pragma unroll
    for (int mi = 0; mi < 4; mi++)
#pragma unroll
        for (int ni = 0; ni < 4; ni++)
#pragma unroll
            for (int r = 0; r < 4; r++) acc[mi][ni][r] = 0.f;

    int rl = lane & 7;
    int ai = lane >> 3;
    int aci = ai >> 1;
    int arow[4];
#pragma unroll
    for (int mi = 0; mi < 4; mi++)
        arow[mi] = (wm * 64 + mi * 16 + (ai & 1) * 8 + rl) * 128;
    int bi = (lane >> 3) & 1;
    int brow[4];
#pragma unroll
    for (int ni = 0; ni < 4; ni++)
        brow[ni] = (wn * 32 + ni * 8 + rl) * 128;

    load_tile_async(sbase + 0 * TILEB, Ahi, m0, 0, tid);
    load_tile_async(sbase + 1 * TILEB, Alo, m0, 0, tid);
    load_tile_async(sbase + 2 * TILEB, Bhi, n0, 0, tid);
    load_tile_async(sbase + 3 * TILEB, Blo, n0, 0, tid);
    CP_COMMIT();

    for (int kt = 0; kt < NCHK; kt++) {
        bool more = (kt + 1) < NCHK;
        if (more) {
            uint32_t nb = sbase + ((kt + 1) & 1) * STAGEB;
            int kk = (kt + 1) * BK;
            load_tile_async(nb + 0 * TILEB, Ahi, m0, kk, tid);
            load_tile_async(nb + 1 * TILEB, Alo, m0, kk, tid);
            load_tile_async(nb + 2 * TILEB, Bhi, n0, kk, tid);
            load_tile_async(nb + 3 * TILEB, Blo, n0, kk, tid);
            CP_COMMIT();
            CP_WAIT(1);
        } else {
            CP_WAIT(0);
        }
        __syncthreads();

        uint32_t st = sbase + (kt & 1) * STAGEB;
#pragma unroll
        for (int t = 0; t < 3; t++) {
            uint32_t uA = st + ((t == 2) ? TILEB : 0);
            uint32_t uB = st + 2 * TILEB + ((t == 1) ? TILEB : 0);
#pragma unroll
            for (int ks = 0; ks < 4; ks++) {
                uint32_t af[4][4], bf[4][2];
#pragma unroll
                for (int mi = 0; mi < 4; mi++)
                    ldsm4(af[mi], uA + arow[mi] + (((ks * 2 + aci) ^ rl) << 4));
#pragma unroll
                for (int ni = 0; ni < 4; ni++)
                    ldsm2(bf[ni], uB + brow[ni] + (((ks * 2 + bi) ^ rl) << 4));
#pragma unroll
                for (int mi = 0; mi < 4; mi++)
#pragma unroll
                    for (int ni = 0; ni < 4; ni++)
                        mma16816(acc[mi][ni], af[mi], bf[ni]);
            }
        }
        __syncthreads();
    }

    int mrow = m0 + wm * 64 + (lane >> 2);
    int ncol = n0 + wn * 32 + (lane & 3) * 2;
#pragma unroll
    for (int mi = 0; mi < 4; mi++) {
#pragma unroll
        for (int ni = 0; ni < 4; ni++) {
            int n = ncol + ni * 8;
#pragma unroll
            for (int half = 0; half < 2; half++) {
                int m = mrow + mi * 16 + half * 8;
                float v0 = acc[mi][ni][half * 2], v1 = acc[mi][ni][half * 2 + 1];
                if (mode == 0) {
                    __nv_bfloat16* Chi = (z == 0) ? g_qhi : (z == 1) ? g_khi : g_vhi;
                    __nv_bfloat16* Clo = (z == 0) ? g_qlo : (z == 1) ? g_klo : g_vlo;
                    __nv_bfloat16 h0 = __float2bfloat16(v0), h1 = __float2bfloat16(v1);
                    __nv_bfloat16 l0 = __float2bfloat16(v0 - __bfloat162float(h0));
                    __nv_bfloat16 l1 = __float2bfloat16(v1 - __bfloat162float(h1));
                    size_t o = ((size_t)(n >> 6) * L_ + m) * 64 + (n & 63);
                    *(__nv_bfloat162*)(Chi + o) = __nv_bfloat162(h0, h1);
                    *(__nv_bfloat162*)(Clo + o) = __nv_bfloat162(l0, l1);
                } else {
                    *(float2*)(out + (size_t)m * E_ + n) = make_float2(v0, v1);
                }
            }
        }
    }
}

// ============================================================================
// Attention, tensor-core version. CTA (p, h) handles 128-row q-tiles {15-p, p}.
// Pass 1: S = QK^T (bf16x3 mma), e = fexp(s*scale + bias) (no max needed:
//         |s| <~ 8), e -> g_e fp16, Z row-sums in regs.
// Pass 2: t = relu(e/Z + tau/idx) -> bf16 hi/lo smem; O += T V (mma, V via
//         ldmatrix.trans); O -> g_ao bf16 hi/lo.
// ============================================================================
#define AQ_HI  0u
#define AQ_LO  16384u
#define AKV    32768u       /* 2 bufs x (hi 8KB + lo 8KB) */
#define ABIAS  65536u
#define AZP    73728u       /* 2 x 128 floats */
#define AINVZ  74752u
#define ATAUT  75264u
#define SMEM_ATT 75776

__global__ __launch_bounds__(256) void attn_kernel(
    const float* __restrict__ bias, const float* __restrict__ tau)
{
    extern __shared__ char smem[];
    uint32_t sb = smem_u32(smem);
    float* sbias = (float*)(smem + ABIAS);
    float* szp   = (float*)(smem + AZP);
    float* sinvz = (float*)(smem + AINVZ);
    float* staut = (float*)(smem + ATAUT);

    int h   = blockIdx.y;
    int prx = blockIdx.x;           // 0..7
    int tid = threadIdx.x;
    int lane = tid & 31, w = tid >> 5;
    int wm = w >> 1, wn = w & 1;    // 4 m-warps x 2 n-warps
    int rl = lane & 7;
    int ai = lane >> 3, aci = ai >> 1;
    int bi = (lane >> 3) & 1;
    float tauh = tau[h];
    const float scale = 0.125f;

    for (int i = tid; i < MBL_ / 4; i += 256)
        *(float4*)&sbias[i * 4] = *(const float4*)&bias[h * MBL_ + i * 4];

    const __nv_bfloat16* qhi = g_qhi + (size_t)h * (L_ * 64);
    const __nv_bfloat16* qlo = g_qlo + (size_t)h * (L_ * 64);
    const __nv_bfloat16* khi = g_khi + (size_t)h * (L_ * 64);
    const __nv_bfloat16* klo = g_klo + (size_t)h * (L_ * 64);
    const __nv_bfloat16* vhi = g_vhi + (size_t)h * (L_ * 64);
    const __nv_bfloat16* vlo = g_vlo + (size_t)h * (L_ * 64);
    __half* eh = g_e + (size_t)h * L_ * L_;

    // frag offsets (within 128-row A region / 64-row B region)
    uint32_t arow[2], brow[4];
#pragma unroll
    for (int mi = 0; mi < 2; mi++)
        arow[mi] = (uint32_t)((wm * 32 + mi * 16 + (ai & 1) * 8 + rl) * 128);
#pragma unroll
    for (int ni = 0; ni < 4; ni++)
        brow[ni] = (uint32_t)((wn * 32 + ni * 8 + rl) * 128);

    for (int which = 0; which < 2; which++) {
        int iq = which ? prx : (15 - prx);
        int q0 = iq * 128;
        int nch = 2 * iq + 2;

        __syncthreads();            // previous tile fully done with smem

        // ---- load Q hi/lo (128 rows) + K chunk 0 ----
#pragma unroll
        for (int it = 0; it < 4; it++) {
            int c = tid + it * 256;
            int row = c >> 3, ch = c & 7;
            uint32_t sw = row * 128 + ((ch ^ (row & 7)) << 4);
            cp16(sb + AQ_HI + sw, qhi + (size_t)(q0 + row) * 64 + ch * 8);
            cp16(sb + AQ_LO + sw, qlo + (size_t)(q0 + row) * 64 + ch * 8);
        }
#pragma unroll
        for (int it = 0; it < 2; it++) {
            int c = tid + it * 256;
            int row = c >> 3, ch = c & 7;
            uint32_t sw = row * 128 + ((ch ^ (row & 7)) << 4);
            cp16(sb + AKV + sw,        khi + (size_t)row * 64 + ch * 8);
            cp16(sb + AKV + 8192 + sw, klo + (size_t)row * 64 + ch * 8);
        }
        CP_COMMIT();

        float rs[2][2] = {{0.f, 0.f}, {0.f, 0.f}};   // per-thread Z partials

        // ==================== PASS 1 ====================
        for (int j = 0; j < nch; j++) {
            int b = j & 1;
            int k0 = j * 64;
            if (j + 1 < nch) {
                uint32_t nb = sb + AKV + (b ^ 1) * 16384;
                int k0n = (j + 1) * 64;
#pragma unroll
                for (int it = 0; it < 2; it++) {
                    int c = tid + it * 256;
                    int row = c >> 3, ch = c & 7;
                    uint32_t sw = row * 128 + ((ch ^ (row & 7)) << 4);
                    cp16(nb + sw,        khi + (size_t)(k0n + row) * 64 + ch * 8);
                    cp16(nb + 8192 + sw, klo + (size_t)(k0n + row) * 64 + ch * 8);
                }
                CP_COMMIT();
                CP_WAIT(1);
            } else {
                CP_WAIT(0);
            }
            __syncthreads();

            float sacc[2][4][4];
#pragma unroll
            for (int mi = 0; mi < 2; mi++)
#pragma unroll
                for (int ni = 0; ni < 4; ni++)
#pragma unroll
                    for (int r = 0; r < 4; r++) sacc[mi][ni][r] = 0.f;

            uint32_t bkhi = sb + AKV + b * 16384;
            uint32_t bklo = bkhi + 8192;
#pragma unroll
            for (int ks = 0; ks < 4; ks++) {
                uint32_t qh[2][4], ql[2][4], kh[4][2], kl[4][2];
                uint32_t choA = (((ks * 2 + aci) ^ rl) << 4);
                uint32_t choB = (((ks * 2 + bi) ^ rl) << 4);
#pragma unroll
                for (int mi = 0; mi < 2; mi++) {
                    ldsm4(qh[mi], sb + AQ_HI + arow[mi] + choA);
                    ldsm4(ql[mi], sb + AQ_LO + arow[mi] + choA);
                }
#pragma unroll
                for (int ni = 0; ni < 4; ni++) {
                    ldsm2(kh[ni], bkhi + brow[ni] + choB);
                    ldsm2(kl[ni], bklo + brow[ni] + choB);
                }
#pragma unroll
                for (int mi = 0; mi < 2; mi++)
#pragma unroll
                    for (int ni = 0; ni < 4; ni++) {
                        mma16816(sacc[mi][ni], qh[mi], kh[ni]);
                        mma16816(sacc[mi][ni], qh[mi], kl[ni]);
                        mma16816(sacc[mi][ni], ql[mi], kh[ni]);
                    }
            }
            __syncthreads();    // K buf b free for prefetch in next iter

            // epilogue: scale + bias + causal, exp, store e, Z partials
#pragma unroll
            for (int mi = 0; mi < 2; mi++) {
                int r = wm * 32 + mi * 16 + (lane >> 2);
#pragma unroll
                for (int ni = 0; ni < 4; ni++) {
                    int c = wn * 32 + ni * 8 + (lane & 3) * 2;
                    int kk = k0 + c;
#pragma unroll
                    for (int hh = 0; hh < 2; hh++) {
                        int qq = q0 + r + hh * 8;
                        float s0 = fmaf(sacc[mi][ni][hh * 2],     scale, 0.f);
                        float s1 = fmaf(sacc[mi][ni][hh * 2 + 1], scale, 0.f);
                        int d0 = qq - kk, d1 = d0 - 1;
                        float e0 = (d0 >= 0) ? fexp(s0 + sbias[d0]) : 0.f;
                        float e1 = (d1 >= 0) ? fexp(s1 + sbias[d1]) : 0.f;
                        *(__half2*)(eh + (size_t)qq * L_ + kk) = __floats2half2_rn(e0, e1);
                        rs[mi][hh] += e0 + e1;
                    }
                }
            }
        }

        // ---- finalize Z (deterministic: quad shuffle + 2-slot combine) ----
#pragma unroll
        for (int mi = 0; mi < 2; mi++)
#pragma unroll
            for (int hh = 0; hh < 2; hh++) {
                rs[mi][hh] += __shfl_xor_sync(0xffffffffu, rs[mi][hh], 1);
                rs[mi][hh] += __shfl_xor_sync(0xffffffffu, rs[mi][hh], 2);
            }
        if ((lane & 3) == 0) {
            int r0 = wm * 32 + (lane >> 2);
            szp[wn * 128 + r0]      = rs[0][0];
            szp[wn * 128 + r0 + 8]  = rs[0][1];
            szp[wn * 128 + r0 + 16] = rs[1][0];
            szp[wn * 128 + r0 + 24] = rs[1][1];
        }
        __syncthreads();
        if (tid < 128) {
            float Zr = szp[tid] + szp[128 + tid];
            sinvz[tid] = 1.f / Zr;
            staut[tid] = tauh / (float)(q0 + tid + 1);
        }
        // prefetch V chunk 0 into buf 0
#pragma unroll
        for (int it = 0; it < 2; it++) {
            int c = tid + it * 256;
            int row = c >> 3, ch = c & 7;
            uint32_t sw = row * 128 + ((ch ^ (row & 7)) << 4);
            cp16(sb + AKV + sw,        vhi + (size_t)row * 64 + ch * 8);
            cp16(sb + AKV + 8192 + sw, vlo + (size_t)row * 64 + ch * 8);
        }
        CP_COMMIT();
        __syncthreads();

        // ==================== PASS 2 ====================
        float oacc[2][4][4];
#pragma unroll
        for (int mi = 0; mi < 2; mi++)
#pragma unroll
            for (int ni = 0; ni < 4; ni++)
#pragma unroll
                for (int r = 0; r < 4; r++) oacc[mi][ni][r] = 0.f;

        for (int j = 0; j < nch; j++) {
            int b = j & 1;
            int k0 = j * 64;
            // build T tile (bf16 hi/lo) in sQ region (prev MMA done: trailing sync)
#pragma unroll
            for (int it = 0; it < 4; it++) {
                int c = tid + it * 256;
                int row = c >> 3, c8 = (c & 7) * 8;
                uint4 ev = *(const uint4*)(eh + (size_t)(q0 + row) * L_ + k0 + c8);
                float iz = sinvz[row], tt = staut[row];
                const __half* ep = (const __half*)&ev;
                uint32_t hiw[4], low[4];
#pragma unroll
                for (int u = 0; u < 4; u++) {
                    float t0 = fmaxf(fmaf(__half2float(ep[2 * u]),     iz, tt), 0.f);
                    float t1 = fmaxf(fmaf(__half2float(ep[2 * u + 1]), iz, tt), 0.f);
                    __nv_bfloat16 h0 = __float2bfloat16(t0), h1 = __float2bfloat16(t1);
                    __nv_bfloat16 l0 = __float2bfloat16(t0 - __bfloat162float(h0));
                    __nv_bfloat16 l1 = __float2bfloat16(t1 - __bfloat162float(h1));
                    __nv_bfloat162 ph(h0, h1), pl(l0, l1);
                    hiw[u] = *(uint32_t*)&ph;
                    low[u] = *(uint32_t*)&pl;
                }
                uint32_t sw = row * 128 + (((c & 7) ^ (row & 7)) << 4);
                *(uint4*)(smem + AQ_HI + sw) = make_uint4(hiw[0], hiw[1], hiw[2], hiw[3]);
                *(uint4*)(smem + AQ_LO + sw) = make_uint4(low[0], low[1], low[2], low[3]);
            }
            if (j + 1 < nch) {
                uint32_t nb = sb + AKV + (b ^ 1) * 16384;
                int k0n = (j + 1) * 64;
#pragma unroll
                for (int it = 0; it < 2; it++) {
                    int c = tid + it * 256;
                    int row = c >> 3, ch = c & 7;
                    uint32_t sw = row * 128 + ((ch ^ (row & 7)) << 4);
                    cp16(nb + sw,        vhi + (size_t)(k0n + row) * 64 + ch * 8);
                    cp16(nb + 8192 + sw, vlo + (size_t)(k0n + row) * 64 + ch * 8);
                }
                CP_COMMIT();
                CP_WAIT(1);
            } else {
                CP_WAIT(0);
            }
            __syncthreads();

            uint32_t bvhi = sb + AKV + b * 16384;
            uint32_t bvlo = bvhi + 8192;
            int krl = lane & 15;
#pragma unroll
            for (int ks = 0; ks < 4; ks++) {
                uint32_t th[2][4], tl[2][4], vh[4][2], vl[4][2];
                uint32_t choA = (((ks * 2 + aci) ^ rl) << 4);
#pragma unroll
                for (int mi = 0; mi < 2; mi++) {
                    ldsm4(th[mi], sb + AQ_HI + arow[mi] + choA);
                    ldsm4(tl[mi], sb + AQ_LO + arow[mi] + choA);
                }
                int kr = ks * 16 + krl;
#pragma unroll
                for (int ni = 0; ni < 4; ni++) {
                    uint32_t off = kr * 128 + (((wn * 4 + ni) ^ (kr & 7)) << 4);
                    ldsm2t(vh[ni], bvhi + off);
                    ldsm2t(vl[ni], bvlo + off);
                }
#pragma unroll
                for (int mi = 0; mi < 2; mi++)
#pragma unroll
                    for (int ni = 0; ni < 4; ni++) {
                        mma16816(oacc[mi][ni], th[mi], vh[ni]);
                        mma16816(oacc[mi][ni], th[mi], vl[ni]);
                        mma16816(oacc[mi][ni], tl[mi], vh[ni]);
                    }
            }
            __syncthreads();    // sT + V buf free for next chunk
        }

        // ---- O -> g_ao bf16 hi/lo ----
#pragma unroll
        for (int mi = 0; mi < 2; mi++) {
#pragma unroll
            for (int ni = 0; ni < 4; ni++) {
                int c = wn * 32 + ni * 8 + (lane & 3) * 2;
#pragma unroll
                for (int hh = 0; hh < 2; hh++) {
                    int q = q0 + wm * 32 + mi * 16 + (lane >> 2) + hh * 8;
                    float v0 = oacc[mi][ni][hh * 2], v1 = oacc[mi][ni][hh * 2 + 1];
                    __nv_bfloat16 h0 = __float2bfloat16(v0), h1 = __float2bfloat16(v1);
                    __nv_bfloat16 l0 = __float2bfloat16(v0 - __bfloat162float(h0));
                    __nv_bfloat16 l1 = __float2bfloat16(v1 - __bfloat162float(h1));
                    size_t o = (size_t)q * E_ + h * 64 + c;
                    *(__nv_bfloat162*)(g_aohi + o) = __nv_bfloat162(h0, h1);
                    *(__nv_bfloat162*)(g_aolo + o) = __nv_bfloat162(l0, l1);
                }
            }
        }
    }
}

// ============================================================================
extern "C" void kernel_launch(void* const* d_in, const int* in_sizes, int n_in,
                              void* d_out, int out_size)
{
    (void)in_sizes; (void)n_in; (void)out_size;
    const float* x    = (const float*)d_in[0];
    const float* Wq   = (const float*)d_in[1];
    const float* Wk   = (const float*)d_in[2];
    const float* Wv   = (const float*)d_in[3];
    const float* Wo   = (const float*)d_in[4];
    const float* bias = (const float*)d_in[5];
    const float* tau  = (const float*)d_in[6];
    float* out = (float*)d_out;

    cudaFuncSetAttribute(mma_gemm, cudaFuncAttributeMaxDynamicSharedMemorySize, SMEM_MMA);
    cudaFuncSetAttribute(attn_kernel, cudaFuncAttributeMaxDynamicSharedMemorySize, SMEM_ATT);

    conv_pair<<<(L_ * E_ / 4) / 256, 256>>>(x,  0);
    conv_pair<<<(E_ * E_ / 4) / 256, 256>>>(Wq, 1);
    conv_pair<<<(E_ * E_ / 4) / 256, 256>>>(Wk, 2);
    conv_pair<<<(E_ * E_ / 4) / 256, 256>>>(Wv, 3);
    conv_pair<<<(E_ * E_ / 4) / 256, 256>>>(Wo, 4);

    mma_gemm<<<dim3(E_ / 128, L_ / 128, 3), 256, SMEM_MMA>>>(0, nullptr);
    attn_kernel<<<dim3(8, H_), 256, SMEM_ATT>>>(bias, tau);
    mma_gemm<<<dim3(E_ / 128, L_ / 128, 1), 256, SMEM_MMA>>>(1, out);
}

// round 7
// speedup vs baseline: 3.4767x; 1.2129x over previous
#include <cuda_runtime.h>
#include <cuda_bf16.h>
#include <cuda_fp16.h>
#include <cstdint>
#include <math.h>

#define L_   2048
#define E_   1024
#define H_   16
#define D_   64
#define MBL_ 2048

// ---------------- device scratch (static; allocation-free) -----------------
__device__ __half g_e[(size_t)H_ * L_ * L_];    // exp(s), unnormalized, fp16

// bf16 hi/lo tensors for the big GEMMs
__device__ __nv_bfloat16 g_xhi[L_ * E_],  g_xlo[L_ * E_];
__device__ __nv_bfloat16 g_whi[4 * E_ * E_], g_wlo[4 * E_ * E_];   // q,k,v,o
__device__ __nv_bfloat16 g_aohi[L_ * E_], g_aolo[L_ * E_];
// fp16 attention operands, [H][L][64]
__device__ __half g_qh[H_ * L_ * D_];
__device__ __half g_kh[H_ * L_ * D_], g_kl[H_ * L_ * D_];
__device__ __half g_vh[H_ * L_ * D_];

// ============================ PTX helpers (sm_80+) ==========================
__device__ __forceinline__ uint32_t smem_u32(const void* p) {
    uint32_t a;
    asm("{ .reg .u64 t; cvta.to.shared.u64 t, %1; cvt.u32.u64 %0, t; }"
        : "=r"(a) : "l"(p));
    return a;
}
__device__ __forceinline__ void cp16(uint32_t dst, const void* src) {
    asm volatile("cp.async.cg.shared.global [%0], [%1], 16;" :: "r"(dst), "l"(src));
}
#define CP_COMMIT()  asm volatile("cp.async.commit_group;" ::: "memory")
#define CP_WAIT(n)   asm volatile("cp.async.wait_group %0;" :: "n"(n) : "memory")

__device__ __forceinline__ void ldsm4(uint32_t a[4], uint32_t addr) {
    asm volatile("ldmatrix.sync.aligned.m8n8.x4.shared.b16 {%0,%1,%2,%3}, [%4];"
        : "=r"(a[0]), "=r"(a[1]), "=r"(a[2]), "=r"(a[3]) : "r"(addr));
}
__device__ __forceinline__ void ldsm2(uint32_t a[2], uint32_t addr) {
    asm volatile("ldmatrix.sync.aligned.m8n8.x2.shared.b16 {%0,%1}, [%2];"
        : "=r"(a[0]), "=r"(a[1]) : "r"(addr));
}
__device__ __forceinline__ void ldsm2t(uint32_t a[2], uint32_t addr) {
    asm volatile("ldmatrix.sync.aligned.m8n8.x2.trans.shared.b16 {%0,%1}, [%2];"
        : "=r"(a[0]), "=r"(a[1]) : "r"(addr));
}
__device__ __forceinline__ void mma_bf(float d[4], const uint32_t a[4], const uint32_t b[2]) {
    asm volatile("mma.sync.aligned.m16n8k16.row.col.f32.bf16.bf16.f32 "
        "{%0,%1,%2,%3}, {%4,%5,%6,%7}, {%8,%9}, {%0,%1,%2,%3};"
        : "+f"(d[0]), "+f"(d[1]), "+f"(d[2]), "+f"(d[3])
        : "r"(a[0]), "r"(a[1]), "r"(a[2]), "r"(a[3]), "r"(b[0]), "r"(b[1]));
}
__device__ __forceinline__ void mma_fp(float d[4], const uint32_t a[4], const uint32_t b[2]) {
    asm volatile("mma.sync.aligned.m16n8k16.row.col.f32.f16.f16.f32 "
        "{%0,%1,%2,%3}, {%4,%5,%6,%7}, {%8,%9}, {%0,%1,%2,%3};"
        : "+f"(d[0]), "+f"(d[1]), "+f"(d[2]), "+f"(d[3])
        : "r"(a[0]), "r"(a[1]), "r"(a[2]), "r"(a[3]), "r"(b[0]), "r"(b[1]));
}

// fast exp on FMA pipe (no MUFU)
__device__ __forceinline__ float fexp(float x) {
    float z  = fmaxf(x, -80.f) * 1.4426950408889634f;
    float fz = z + 12582912.f;
    int   n  = __float_as_int(fz) - 0x4B400000;
    float f  = z - (float)n;
    float p  = 1.3333558146428443e-3f;
    p = fmaf(p, f, 9.6181291076284772e-3f);
    p = fmaf(p, f, 5.5504108664821580e-2f);
    p = fmaf(p, f, 2.4022650695910071e-1f);
    p = fmaf(p, f, 6.9314718055994531e-1f);
    p = fmaf(p, f, 1.0f);
    return p * __int_as_float((n + 127) << 23);
}

// ============================================================================
// fp32 -> bf16 hi/lo split, all 5 tensors in one launch.
// blocks [0,2048): x;  [2048, 2048+4*1024): W q,k,v,o
// ============================================================================
__global__ __launch_bounds__(256) void conv_all(
    const float* __restrict__ x,  const float* __restrict__ Wq,
    const float* __restrict__ Wk, const float* __restrict__ Wv,
    const float* __restrict__ Wo)
{
    int b = blockIdx.x;
    const float* s;
    __nv_bfloat16 *hi, *lo;
    int off;
    if (b < 2048) { s = x; hi = g_xhi; lo = g_xlo; off = b; }
    else {
        int wsel = (b - 2048) >> 10;
        off = (b - 2048) & 1023;
        s = (wsel == 0) ? Wq : (wsel == 1) ? Wk : (wsel == 2) ? Wv : Wo;
        hi = g_whi + (size_t)wsel * (E_ * E_);
        lo = g_wlo + (size_t)wsel * (E_ * E_);
    }
    int i = off * 256 + threadIdx.x;
    float4 v = ((const float4*)s)[i];
    __nv_bfloat16 h0 = __float2bfloat16(v.x);
    __nv_bfloat16 h1 = __float2bfloat16(v.y);
    __nv_bfloat16 h2 = __float2bfloat16(v.z);
    __nv_bfloat16 h3 = __float2bfloat16(v.w);
    __nv_bfloat16 l0 = __float2bfloat16(v.x - __bfloat162float(h0));
    __nv_bfloat16 l1 = __float2bfloat16(v.y - __bfloat162float(h1));
    __nv_bfloat16 l2 = __float2bfloat16(v.z - __bfloat162float(h2));
    __nv_bfloat16 l3 = __float2bfloat16(v.w - __bfloat162float(h3));
    __nv_bfloat162* h2p = (__nv_bfloat162*)(hi + i * 4);
    __nv_bfloat162* l2p = (__nv_bfloat162*)(lo + i * 4);
    h2p[0] = __nv_bfloat162(h0, h1); h2p[1] = __nv_bfloat162(h2, h3);
    l2p[0] = __nv_bfloat162(l0, l1); l2p[1] = __nv_bfloat162(l2, l3);
}

// ============================================================================
// bf16x3 GEMM on mma.sync: C[128,128] = A[M,K] * B[N,K]^T
// mode 0: x*W[z] -> q fp16 / k fp16 hi,lo / v fp16 in [H][L][64]
// mode 1: ao*Wo -> out fp32
// ============================================================================
#define BK    64
#define NCHK  (E_ / BK)
#define TILEB (128 * BK * 2)
#define STAGEB (4 * TILEB)
#define SMEM_MMA (2 * STAGEB)

__device__ __forceinline__ void load_tile_async(
    uint32_t dst, const __nv_bfloat16* src, int row0, int kt, int tid)
{
#pragma unroll
    for (int it = 0; it < 4; it++) {
        int c = tid + it * 256;
        int row = c >> 3;
        int ch  = c & 7;
        const __nv_bfloat16* sp = src + (size_t)(row0 + row) * E_ + kt + ch * 8;
        uint32_t sw = row * 128 + ((ch ^ (row & 7)) << 4);
        cp16(dst + sw, sp);
    }
}

__global__ __launch_bounds__(256) void mma_gemm(int mode, float* __restrict__ out)
{
    extern __shared__ char smem[];
    uint32_t sbase = smem_u32(smem);
    int tid  = threadIdx.x;
    int lane = tid & 31;
    int w    = tid >> 5;
    int wm   = w >> 2;
    int wn   = w & 3;
    int z    = blockIdx.z;
    int m0   = blockIdx.y * 128;
    int n0   = blockIdx.x * 128;

    const __nv_bfloat16* Ahi = (mode == 0) ? g_xhi : g_aohi;
    const __nv_bfloat16* Alo = (mode == 0) ? g_xlo : g_aolo;
    int wsel = (mode == 0) ? z : 3;
    const __nv_bfloat16* Bhi = g_whi + (size_t)wsel * (E_ * E_);
    const __nv_bfloat16* Blo = g_wlo + (size_t)wsel * (E_ * E_);

    float acc[4][4][4];
#pragma unroll
    for (int mi = 0; mi < 4; mi++)
#pragma unroll
        for (int ni = 0; ni < 4; ni++)
#pragma unroll
            for (int r = 0; r < 4; r++) acc[mi][ni][r] = 0.f;

    int rl = lane & 7;
    int ai = lane >> 3;
    int aci = ai >> 1;
    int arow[4];
#pragma unroll
    for (int mi = 0; mi < 4; mi++)
        arow[mi] = (wm * 64 + mi * 16 + (ai & 1) * 8 + rl) * 128;
    int bi = (lane >> 3) & 1;
    int brow[4];
#pragma unroll
    for (int ni = 0; ni < 4; ni++)
        brow[ni] = (wn * 32 + ni * 8 + rl) * 128;

    load_tile_async(sbase + 0 * TILEB, Ahi, m0, 0, tid);
    load_tile_async(sbase + 1 * TILEB, Alo, m0, 0, tid);
    load_tile_async(sbase + 2 * TILEB, Bhi, n0, 0, tid);
    load_tile_async(sbase + 3 * TILEB, Blo, n0, 0, tid);
    CP_COMMIT();

    for (int kt = 0; kt < NCHK; kt++) {
        bool more = (kt + 1) < NCHK;
        if (more) {
            uint32_t nb = sbase + ((kt + 1) & 1) * STAGEB;
            int kk = (kt + 1) * BK;
            load_tile_async(nb + 0 * TILEB, Ahi, m0, kk, tid);
            load_tile_async(nb + 1 * TILEB, Alo, m0, kk, tid);
            load_tile_async(nb + 2 * TILEB, Bhi, n0, kk, tid);
            load_tile_async(nb + 3 * TILEB, Blo, n0, kk, tid);
            CP_COMMIT();
            CP_WAIT(1);
        } else {
            CP_WAIT(0);
        }
        __syncthreads();

        uint32_t st = sbase + (kt & 1) * STAGEB;
#pragma unroll
        for (int t = 0; t < 3; t++) {
            uint32_t uA = st + ((t == 2) ? TILEB : 0);
            uint32_t uB = st + 2 * TILEB + ((t == 1) ? TILEB : 0);
#pragma unroll
            for (int ks = 0; ks < 4; ks++) {
                uint32_t af[4][4], bf[4][2];
#pragma unroll
                for (int mi = 0; mi < 4; mi++)
                    ldsm4(af[mi], uA + arow[mi] + (((ks * 2 + aci) ^ rl) << 4));
#pragma unroll
                for (int ni = 0; ni < 4; ni++)
                    ldsm2(bf[ni], uB + brow[ni] + (((ks * 2 + bi) ^ rl) << 4));
#pragma unroll
                for (int mi = 0; mi < 4; mi++)
#pragma unroll
                    for (int ni = 0; ni < 4; ni++)
                        mma_bf(acc[mi][ni], af[mi], bf[ni]);
            }
        }
        __syncthreads();
    }

    int mrow = m0 + wm * 64 + (lane >> 2);
    int ncol = n0 + wn * 32 + (lane & 3) * 2;
#pragma unroll
    for (int mi = 0; mi < 4; mi++) {
#pragma unroll
        for (int ni = 0; ni < 4; ni++) {
            int n = ncol + ni * 8;
#pragma unroll
            for (int half = 0; half < 2; half++) {
                int m = mrow + mi * 16 + half * 8;
                float v0 = acc[mi][ni][half * 2], v1 = acc[mi][ni][half * 2 + 1];
                if (mode == 0) {
                    size_t o = ((size_t)(n >> 6) * L_ + m) * 64 + (n & 63);
                    if (z == 0) {
                        *(__half2*)(g_qh + o) = __floats2half2_rn(v0, v1);
                    } else if (z == 1) {
                        __half h0 = __float2half_rn(v0), h1 = __float2half_rn(v1);
                        __half l0 = __float2half_rn(v0 - __half2float(h0));
                        __half l1 = __float2half_rn(v1 - __half2float(h1));
                        *(__half2*)(g_kh + o) = __halves2half2(h0, h1);
                        *(__half2*)(g_kl + o) = __halves2half2(l0, l1);
                    } else {
                        *(__half2*)(g_vh + o) = __floats2half2_rn(v0, v1);
                    }
                } else {
                    *(float2*)(out + (size_t)m * E_ + n) = make_float2(v0, v1);
                }
            }
        }
    }
}

// ============================================================================
// Attention. CTA (p, h) handles 64-row q-tiles {31-p, p} (33 chunks total).
// 256 thr = 8 warps: 4 m-warps x 2 n-warps, warp tile 16x32.
// Pass 1: S = q*(kh+kl) fp16 mma (2 terms), e = fexp(s*scale+bias) -> g_e fp16,
//         Z row sums. Pass 2: t = relu(e*invZ + tau/idx) fp16 -> smem;
//         O += T*V (1 term, V via ldmatrix.trans); O -> g_ao bf16 hi/lo.
// ============================================================================
#define AT_    0u          /* 8 KB: Q (pass1) / T (pass2) */
#define AKV_   8192u       /* 2 bufs x 16 KB (K: hi 8K + lo 8K; V: hi only) */
#define ABIAS_ 40960u      /* 8 KB */
#define AZP_   49152u      /* 2 x 64 floats */
#define AINVZ_ 49664u
#define ATAUT_ 49920u
#define SMEM_ATT 50176

__global__ __launch_bounds__(256) void attn_kernel(
    const float* __restrict__ bias, const float* __restrict__ tau)
{
    extern __shared__ char smem[];
    uint32_t sb = smem_u32(smem);
    float* sbias = (float*)(smem + ABIAS_);
    float* szp   = (float*)(smem + AZP_);
    float* sinvz = (float*)(smem + AINVZ_);
    float* staut = (float*)(smem + ATAUT_);

    int h   = blockIdx.y;
    int p   = blockIdx.x;           // 0..15
    int tid = threadIdx.x;
    int lane = tid & 31, w = tid >> 5;
    int wm = w >> 1, wn = w & 1;    // 4 m-warps x 2 n-warps
    int rl = lane & 7;
    int ai = lane >> 3, aci = ai >> 1, bi = ai & 1;
    float tauh = tau[h];
    const float scale = 0.125f;

    for (int i = tid; i < MBL_ / 4; i += 256)
        *(float4*)&sbias[i * 4] = *(const float4*)&bias[h * MBL_ + i * 4];

    const __half* qh = g_qh + (size_t)h * (L_ * 64);
    const __half* kh = g_kh + (size_t)h * (L_ * 64);
    const __half* kl = g_kl + (size_t)h * (L_ * 64);
    const __half* vh = g_vh + (size_t)h * (L_ * 64);
    __half* eh = g_e + (size_t)h * L_ * L_;

    uint32_t arow = (uint32_t)((wm * 16 + (ai & 1) * 8 + rl) * 128);
    uint32_t brow[4];
#pragma unroll
    for (int ni = 0; ni < 4; ni++)
        brow[ni] = (uint32_t)((wn * 32 + ni * 8 + rl) * 128);

    for (int which = 0; which < 2; which++) {
        int iq = which ? p : (31 - p);
        int q0 = iq * 64;
        int nch = iq + 1;

        __syncthreads();            // previous tile fully done with smem

        // ---- load Q (fp16, 64 rows x 128B) + K chunk 0 hi/lo ----
#pragma unroll
        for (int it = 0; it < 2; it++) {
            int c = tid + it * 256;
            int row = c >> 3, ch = c & 7;
            uint32_t sw = row * 128 + ((ch ^ (row & 7)) << 4);
            cp16(sb + AT_ + sw, qh + (size_t)(q0 + row) * 64 + ch * 8);
            cp16(sb + AKV_ + sw,        kh + (size_t)row * 64 + ch * 8);
            cp16(sb + AKV_ + 8192 + sw, kl + (size_t)row * 64 + ch * 8);
        }
        CP_COMMIT();

        float rs[2] = {0.f, 0.f};

        // ==================== PASS 1 ====================
        for (int j = 0; j < nch; j++) {
            int b = j & 1;
            int k0 = j * 64;
            if (j + 1 < nch) {
                uint32_t nb = sb + AKV_ + (b ^ 1) * 16384;
                int k0n = (j + 1) * 64;
#pragma unroll
                for (int it = 0; it < 2; it++) {
                    int c = tid + it * 256;
                    int row = c >> 3, ch = c & 7;
                    uint32_t sw = row * 128 + ((ch ^ (row & 7)) << 4);
                    cp16(nb + sw,        kh + (size_t)(k0n + row) * 64 + ch * 8);
                    cp16(nb + 8192 + sw, kl + (size_t)(k0n + row) * 64 + ch * 8);
                }
                CP_COMMIT();
                CP_WAIT(1);
            } else {
                CP_WAIT(0);
            }
            __syncthreads();

            float sacc[4][4];
#pragma unroll
            for (int ni = 0; ni < 4; ni++)
#pragma unroll
                for (int r = 0; r < 4; r++) sacc[ni][r] = 0.f;

            uint32_t bkh = sb + AKV_ + b * 16384;
            uint32_t bkl = bkh + 8192;
#pragma unroll
            for (int ks = 0; ks < 4; ks++) {
                uint32_t qf[4], khf[4][2], klf[4][2];
                uint32_t choA = (((ks * 2 + aci) ^ rl) << 4);
                uint32_t choB = (((ks * 2 + bi) ^ rl) << 4);
                ldsm4(qf, sb + AT_ + arow + choA);
#pragma unroll
                for (int ni = 0; ni < 4; ni++) {
                    ldsm2(khf[ni], bkh + brow[ni] + choB);
                    ldsm2(klf[ni], bkl + brow[ni] + choB);
                }
#pragma unroll
                for (int ni = 0; ni < 4; ni++) {
                    mma_fp(sacc[ni], qf, khf[ni]);
                    mma_fp(sacc[ni], qf, klf[ni]);
                }
            }
            __syncthreads();    // K buf b reusable

            // epilogue: scale + bias + causal, exp, store e, Z partials
            int r = wm * 16 + (lane >> 2);
#pragma unroll
            for (int ni = 0; ni < 4; ni++) {
                int kk = k0 + wn * 32 + ni * 8 + (lane & 3) * 2;
#pragma unroll
                for (int hh = 0; hh < 2; hh++) {
                    int qq = q0 + r + hh * 8;
                    float s0 = sacc[ni][hh * 2]     * scale;
                    float s1 = sacc[ni][hh * 2 + 1] * scale;
                    int d0 = qq - kk, d1 = d0 - 1;
                    float e0 = (d0 >= 0) ? fexp(s0 + sbias[d0]) : 0.f;
                    float e1 = (d1 >= 0) ? fexp(s1 + sbias[d1]) : 0.f;
                    *(__half2*)(eh + (size_t)qq * L_ + kk) = __floats2half2_rn(e0, e1);
                    rs[hh] += e0 + e1;
                }
            }
        }

        // ---- finalize Z ----
#pragma unroll
        for (int hh = 0; hh < 2; hh++) {
            rs[hh] += __shfl_xor_sync(0xffffffffu, rs[hh], 1);
            rs[hh] += __shfl_xor_sync(0xffffffffu, rs[hh], 2);
        }
        if ((lane & 3) == 0) {
            int r0 = wm * 16 + (lane >> 2);
            szp[wn * 64 + r0]     = rs[0];
            szp[wn * 64 + r0 + 8] = rs[1];
        }
        __syncthreads();
        if (tid < 64) {
            float Zr = szp[tid] + szp[64 + tid];
            sinvz[tid] = 1.f / Zr;
            staut[tid] = tauh / (float)(q0 + tid + 1);
        }
        // prefetch V chunk 0 into buf 0
#pragma unroll
        for (int it = 0; it < 2; it++) {
            int c = tid + it * 256;
            int row = c >> 3, ch = c & 7;
            uint32_t sw = row * 128 + ((ch ^ (row & 7)) << 4);
            cp16(sb + AKV_ + sw, vh + (size_t)row * 64 + ch * 8);
        }
        CP_COMMIT();
        __syncthreads();

        // ==================== PASS 2 ====================
        float oacc[4][4];
#pragma unroll
        for (int ni = 0; ni < 4; ni++)
#pragma unroll
            for (int r = 0; r < 4; r++) oacc[ni][r] = 0.f;

        for (int j = 0; j < nch; j++) {
            int b = j & 1;
            int k0 = j * 64;
            // build T tile (fp16) in AT_ (prev chunk's MMA done: trailing sync)
#pragma unroll
            for (int it = 0; it < 2; it++) {
                int c = tid + it * 256;
                int row = c >> 3, ch = c & 7;
                uint4 ev = *(const uint4*)(eh + (size_t)(q0 + row) * L_ + k0 + ch * 8);
                float iz = sinvz[row], tt = staut[row];
                const __half2* ep = (const __half2*)&ev;
                uint32_t tw[4];
#pragma unroll
                for (int u = 0; u < 4; u++) {
                    float2 e2 = __half22float2(ep[u]);
                    float t0 = fmaxf(fmaf(e2.x, iz, tt), 0.f);
                    float t1 = fmaxf(fmaf(e2.y, iz, tt), 0.f);
                    __half2 tp = __floats2half2_rn(t0, t1);
                    tw[u] = *(uint32_t*)&tp;
                }
                uint32_t sw = row * 128 + ((ch ^ (row & 7)) << 4);
                *(uint4*)(smem + AT_ + sw) = make_uint4(tw[0], tw[1], tw[2], tw[3]);
            }
            if (j + 1 < nch) {
                uint32_t nb = sb + AKV_ + (b ^ 1) * 16384;
                int k0n = (j + 1) * 64;
#pragma unroll
                for (int it = 0; it < 2; it++) {
                    int c = tid + it * 256;
                    int row = c >> 3, ch = c & 7;
                    uint32_t sw = row * 128 + ((ch ^ (row & 7)) << 4);
                    cp16(nb + sw, vh + (size_t)(k0n + row) * 64 + ch * 8);
                }
                CP_COMMIT();
                CP_WAIT(1);
            } else {
                CP_WAIT(0);
            }
            __syncthreads();

            uint32_t bv = sb + AKV_ + b * 16384;
            int krl = lane & 15;
#pragma unroll
            for (int ks = 0; ks < 4; ks++) {
                uint32_t tf[4], vf[4][2];
                uint32_t choA = (((ks * 2 + aci) ^ rl) << 4);
                ldsm4(tf, sb + AT_ + arow + choA);
                int kr = ks * 16 + krl;
#pragma unroll
                for (int ni = 0; ni < 4; ni++) {
                    uint32_t off = kr * 128 + (((wn * 4 + ni) ^ (kr & 7)) << 4);
                    ldsm2t(vf[ni], bv + off);
                }
#pragma unroll
                for (int ni = 0; ni < 4; ni++)
                    mma_fp(oacc[ni], tf, vf[ni]);
            }
            __syncthreads();    // T + V buf free for next chunk
        }

        // ---- O -> g_ao bf16 hi/lo ----
#pragma unroll
        for (int ni = 0; ni < 4; ni++) {
            int c = wn * 32 + ni * 8 + (lane & 3) * 2;
#pragma unroll
            for (int hh = 0; hh < 2; hh++) {
                int q = q0 + wm * 16 + (lane >> 2) + hh * 8;
                float v0 = oacc[ni][hh * 2], v1 = oacc[ni][hh * 2 + 1];
                __nv_bfloat16 h0 = __float2bfloat16(v0), h1 = __float2bfloat16(v1);
                __nv_bfloat16 l0 = __float2bfloat16(v0 - __bfloat162float(h0));
                __nv_bfloat16 l1 = __float2bfloat16(v1 - __bfloat162float(h1));
                size_t o = (size_t)q * E_ + h * 64 + c;
                *(__nv_bfloat162*)(g_aohi + o) = __nv_bfloat162(h0, h1);
                *(__nv_bfloat162*)(g_aolo + o) = __nv_bfloat162(l0, l1);
            }
        }
    }
}

// ============================================================================
extern "C" void kernel_launch(void* const* d_in, const int* in_sizes, int n_in,
                              void* d_out, int out_size)
{
    (void)in_sizes; (void)n_in; (void)out_size;
    const float* x    = (const float*)d_in[0];
    const float* Wq   = (const float*)d_in[1];
    const float* Wk   = (const float*)d_in[2];
    const float* Wv   = (const float*)d_in[3];
    const float* Wo   = (const float*)d_in[4];
    const float* bias = (const float*)d_in[5];
    const float* tau  = (const float*)d_in[6];
    float* out = (float*)d_out;

    cudaFuncSetAttribute(mma_gemm, cudaFuncAttributeMaxDynamicSharedMemorySize, SMEM_MMA);
    cudaFuncSetAttribute(attn_kernel, cudaFuncAttributeMaxDynamicSharedMemorySize, SMEM_ATT);

    conv_all<<<2048 + 4 * 1024, 256>>>(x, Wq, Wk, Wv, Wo);
    mma_gemm<<<dim3(E_ / 128, L_ / 128, 3), 256, SMEM_MMA>>>(0, nullptr);
    attn_kernel<<<dim3(16, H_), 256, SMEM_ATT>>>(bias, tau);
    mma_gemm<<<dim3(E_ / 128, L_ / 128, 1), 256, SMEM_MMA>>>(1, out);
}